// round 11
// baseline (speedup 1.0000x reference)
#include <cuda_runtime.h>
#include <cuda_bf16.h>
#include <cstdint>

// FlowBasedDensityPotential: energy = 0.5 * sum(|grad phi|^2), central diffs
// (one-sided at boundaries) on 2048x2048 f32. 'pos' input is dead.
//
// R11: TMA bulk-copy, de-serialized. R10 (256 CTAs, two chained mbar waits)
// showed occ 21% / issue 15%: ~2 outstanding copies per SM, engine never
// ramped. Now: 512 CTAs, ONE 48KB bulk copy each (6-row halo tile), one wait,
// 4 CTAs/SM resident -> ~3.5 independent copies in flight per SM (~25MB
// chip-wide). Compute = rolling 3-row register window from smem (R4 scheme).

#define NX 2048
#define NY 2048
#define BLOCK 256
#define ROWS_PER_CTA 4
#define NUM_BLOCKS (NX / ROWS_PER_CTA)     // 512
#define PITCH NY
#define ROW_BYTES (NY * 4)                  // 8192
#define SROWS 6                             // 4 computed + 2 halo
#define TILE_BYTES (SROWS * ROW_BYTES)      // 49152
#define FINAL_SCALE 524288.0                // 0.5 * (1/(2h))^2

__device__ double       g_partials[NUM_BLOCKS];
__device__ unsigned int g_ticket = 0;

extern __shared__ float s_tile[];           // SROWS * PITCH floats

__device__ __forceinline__ void mbar_init(unsigned int mbar, unsigned int cnt) {
    asm volatile("mbarrier.init.shared.b64 [%0], %1;" :: "r"(mbar), "r"(cnt) : "memory");
}
__device__ __forceinline__ void mbar_expect_tx(unsigned int mbar, unsigned int bytes) {
    asm volatile("mbarrier.arrive.expect_tx.shared.b64 _, [%0], %1;"
                 :: "r"(mbar), "r"(bytes) : "memory");
}
__device__ __forceinline__ void bulk_g2s(unsigned int sdst, const void* gsrc,
                                         unsigned int bytes, unsigned int mbar) {
    asm volatile("cp.async.bulk.shared::cta.global.mbarrier::complete_tx::bytes "
                 "[%0], [%1], %2, [%3];"
                 :: "r"(sdst), "l"(gsrc), "r"(bytes), "r"(mbar) : "memory");
}
__device__ __forceinline__ void mbar_wait(unsigned int mbar, unsigned int phase) {
    asm volatile("{\n\t"
                 ".reg .pred p;\n\t"
                 "WL%=:\n\t"
                 "mbarrier.try_wait.parity.shared.b64 p, [%0], %1;\n\t"
                 "@!p bra WL%=;\n\t"
                 "}" :: "r"(mbar), "r"(phase) : "memory");
}

__global__ void __launch_bounds__(BLOCK, 4)
flow_energy_kernel(const float* __restrict__ phi, float* __restrict__ out)
{
    __shared__ __align__(8) unsigned long long s_bar;
    __shared__ float  s_warp[BLOCK / 32];
    __shared__ double s_dwarp[BLOCK / 32];
    __shared__ bool   s_is_last;

    const int tid = threadIdx.x;
    const int b   = blockIdx.x;
    const int r0  = b * ROWS_PER_CTA;

    const unsigned int sbase = (unsigned int)__cvta_generic_to_shared(s_tile);
    const unsigned int bar   = (unsigned int)__cvta_generic_to_shared(&s_bar);

    if (tid == 0)
        mbar_init(bar, 1);
    __syncthreads();

    if (tid == 0) {
        // One bulk copy: global rows max(r0-1,0) .. min(r0+4, NX-1)
        // into smem slots (b==0 ? 1 : 0) .. ; clamped slots unused.
        const int gs   = (b == 0) ? 0 : r0 - 1;
        const int slot = (b == 0) ? 1 : 0;
        const int ge   = (b == NUM_BLOCKS - 1) ? NX - 1 : r0 + 4;
        const unsigned int bytes = (unsigned int)((ge - gs + 1) * ROW_BYTES);
        mbar_expect_tx(bar, bytes);
        bulk_g2s(sbase + (unsigned int)(slot * ROW_BYTES),
                 phi + (size_t)gs * NY, bytes, bar);
    }

    mbar_wait(bar, 0);

    float acc = 0.0f;

    // 512 column chunks, 2 per thread; each walks 4 rows with a rolling window.
    #pragma unroll
    for (int pass = 0; pass < 2; ++pass) {
        const int cg = tid + pass * BLOCK;    // 0..511
        const int c  = cg * 4;                // first col of this float4 chunk

        float4 w[6];
        #pragma unroll
        for (int k = 0; k < 6; ++k)
            w[k] = *reinterpret_cast<const float4*>(s_tile + k * PITCH + c);

        #pragma unroll
        for (int r = 0; r < ROWS_PER_CTA; ++r) {
            const int slot = 1 + r;
            const int gi   = r0 + r;
            const float4 up   = w[r];
            const float4 cur  = w[r + 1];
            const float4 down = w[r + 2];

            float ex, ey, ez, ew;
            if (gi == 0) {
                ex = (down.x - cur.x) * 2.0f;
                ey = (down.y - cur.y) * 2.0f;
                ez = (down.z - cur.z) * 2.0f;
                ew = (down.w - cur.w) * 2.0f;
            } else if (gi == NX - 1) {
                ex = (cur.x - up.x) * 2.0f;
                ey = (cur.y - up.y) * 2.0f;
                ez = (cur.z - up.z) * 2.0f;
                ew = (cur.w - up.w) * 2.0f;
            } else {
                ex = down.x - up.x;
                ey = down.y - up.y;
                ez = down.z - up.z;
                ew = down.w - up.w;
            }

            // y halos from smem; index clamped to stay in-bounds (clamped
            // values are select-discarded, never arithmetic inputs).
            const float left  = s_tile[slot * PITCH + c - 1 + (c == 0 ? 1 : 0)];
            const float right = s_tile[slot * PITCH + c + 4 - (c + 4 == NY ? 1 : 0)];

            const float d0 = (c == 0)      ? (cur.y - cur.x) * 2.0f : (cur.y - left);
            const float d1 = cur.z - cur.x;
            const float d2 = cur.w - cur.y;
            const float d3 = (c + 4 == NY) ? (cur.w - cur.z) * 2.0f : (right - cur.z);

            acc += ex * ex + d0 * d0;
            acc += ey * ey + d1 * d1;
            acc += ez * ez + d2 * d2;
            acc += ew * ew + d3 * d3;
        }
    }

    // ---- block reduction ----
    #pragma unroll
    for (int off = 16; off; off >>= 1)
        acc += __shfl_xor_sync(0xffffffffu, acc, off);

    if ((tid & 31) == 0)
        s_warp[tid >> 5] = acc;
    __syncthreads();

    if (tid < 32) {
        float v = (tid < BLOCK / 32) ? s_warp[tid] : 0.0f;
        #pragma unroll
        for (int off = 4; off; off >>= 1)
            v += __shfl_xor_sync(0xffffffffu, v, off);
        if (tid == 0) {
            g_partials[blockIdx.x] = (double)v;
            __threadfence();
            unsigned int tk = atomicAdd(&g_ticket, 1u);
            s_is_last = (tk == (unsigned int)(gridDim.x - 1));
        }
    }
    __syncthreads();

    // ---- last block: sum 512 double partials, scale, write, reset ----
    if (s_is_last) {
        double d = 0.0;
        for (int k = tid; k < NUM_BLOCKS; k += BLOCK)
            d += g_partials[k];
        #pragma unroll
        for (int off = 16; off; off >>= 1)
            d += __shfl_xor_sync(0xffffffffu, d, off);

        if ((tid & 31) == 0)
            s_dwarp[tid >> 5] = d;
        __syncthreads();
        if (tid < 32) {
            double v = (tid < BLOCK / 32) ? s_dwarp[tid] : 0.0;
            #pragma unroll
            for (int off = 4; off; off >>= 1)
                v += __shfl_xor_sync(0xffffffffu, v, off);
            if (tid == 0) {
                out[0] = (float)(v * FINAL_SCALE);
                g_ticket = 0;   // reset for next (graph-replayed) launch
            }
        }
    }
}

extern "C" void kernel_launch(void* const* d_in, const int* in_sizes, int n_in,
                              void* d_out, int out_size)
{
    // Select phi by element count (2048*2048); 'pos' (2,000,000 elems) unused.
    const float* phi = nullptr;
    for (int i = 0; i < n_in; ++i) {
        if (in_sizes[i] == NX * NY) { phi = (const float*)d_in[i]; break; }
    }
    if (!phi) phi = (const float*)d_in[n_in - 1];

    static bool attr_done = false;
    if (!attr_done) {
        cudaFuncSetAttribute(flow_energy_kernel,
                             cudaFuncAttributeMaxDynamicSharedMemorySize,
                             TILE_BYTES);
        attr_done = true;
    }

    flow_energy_kernel<<<NUM_BLOCKS, BLOCK, TILE_BYTES>>>(phi, (float*)d_out);
}